// round 1
// baseline (speedup 1.0000x reference)
#include <cuda_runtime.h>
#include <math.h>

#define Bq   4
#define Nq   4096
#define Cq   256
#define DKq  64
#define NROWS (Bq*Nq)          // 16384
#define NEG_BIG (-3.402823466e38f)

// scratch for projected Q / K (device globals: allocation-free)
__device__ float g_Q[NROWS*DKq];
__device__ float g_K[NROWS*DKq];

__device__ __forceinline__ void fma2(unsigned long long &acc,
                                     unsigned long long a, unsigned long long b) {
    asm volatile("fma.rn.f32x2 %0, %1, %2, %0;" : "+l"(acc) : "l"(a), "l"(b));
}

// =====================================================================
// Kernel 1: projections  Q = x @ Wq,  K = x @ Wk
// grid 256 (64 global rows each), block 256 (16x16), 4x8 micro, f32x2 d-pairs
// =====================================================================
#define XP 36   // smem pitch (floats): 36*4B=144B (16B aligned), bank stride 4

__global__ __launch_bounds__(256) void proj_kernel(
        const float* __restrict__ x,
        const float* __restrict__ Wq,
        const float* __restrict__ Wk) {
    __shared__ float Xs[64*XP];
    __shared__ float Ws[128*XP];
    int t  = threadIdx.x;
    int rb = blockIdx.x;
    int b  = rb >> 6;
    int n0 = (rb & 63) << 6;
    int tx = t & 15, ty = t >> 4;

    unsigned long long acc[4][8];
#pragma unroll
    for (int i = 0; i < 4; i++)
#pragma unroll
        for (int j = 0; j < 8; j++) acc[i][j] = 0ull;

    const float* xb = x + (size_t)(b*Nq + n0) * Cq;

    for (int c0 = 0; c0 < Cq; c0 += 32) {
        // X tile: 64 rows x 32 cols
#pragma unroll
        for (int s = 0; s < 2; s++) {
            int li = t + s*256;
            int r = li >> 3, cq = li & 7;
            float4 v = *(const float4*)(xb + (size_t)r*Cq + c0 + cq*4);
            *(float4*)(&Xs[r*XP + cq*4]) = v;
        }
        // W tiles, stored transposed: Ws[col][c]
#pragma unroll
        for (int s = 0; s < 16; s++) {
            int li  = t + s*256;      // 0..4095
            int mat = li >> 11;       // 0=Wq, 1=Wk
            int rem = li & 2047;
            int cc  = rem >> 6;       // 0..31
            int jj  = rem & 63;
            const float* W = mat ? Wk : Wq;
            Ws[(mat*64 + jj)*XP + cc] = W[(size_t)(c0+cc)*DKq + jj];
        }
        __syncthreads();
#pragma unroll
        for (int cc = 0; cc < 32; cc += 4) {
            ulonglong2 qv[4];
#pragma unroll
            for (int i = 0; i < 4; i++)
                qv[i] = *(const ulonglong2*)(&Xs[(ty + 16*i)*XP + cc]);
#pragma unroll
            for (int j = 0; j < 8; j++) {
                ulonglong2 wv = *(const ulonglong2*)(&Ws[(tx + 16*j)*XP + cc]);
#pragma unroll
                for (int i = 0; i < 4; i++) {
                    fma2(acc[i][j], qv[i].x, wv.x);
                    fma2(acc[i][j], qv[i].y, wv.y);
                }
            }
        }
        __syncthreads();
    }
#pragma unroll
    for (int i = 0; i < 4; i++) {
        int m = rb*64 + ty + 16*i;
#pragma unroll
        for (int j = 0; j < 8; j++) {
            int col = tx + 16*j;
            union { unsigned long long u; float2 f; } cv; cv.u = acc[i][j];
            float v = cv.f.x + cv.f.y;
            if (col < 64) g_Q[(size_t)m*DKq + col]        = v;
            else          g_K[(size_t)m*DKq + (col - 64)] = v;
        }
    }
}

// =====================================================================
// Kernel 2: S = Q K^T * scale (tiled), fused top-8 + softmax + sparse write
// grid 256 (64 rows each), block 256 (16x16), 4x4 micro, f32x2 d-pairs,
// cp.async double-buffered K tiles, S staged in smem for the top-k scan,
// zero-fill of the 64 output rows interleaved with the GEMM loop.
// =====================================================================
#define QP   68                 // smem pitch: 272B (16B aligned), bank stride 4
#define KSF  (64*QP)            // floats per K buffer
#define SM2_BYTES (4*64*QP*4)   // Qs + Ks0 + Ks1 + Ss = 69632 B

__global__ __launch_bounds__(256, 2) void edge_kernel(float* __restrict__ out) {
    extern __shared__ float sm[];
    float* Qs  = sm;
    float* Ks0 = sm + KSF;           // two buffers: Ks0, Ks0+KSF
    float* Ss  = sm + 3*KSF;

    int t  = threadIdx.x;
    int rb = blockIdx.x;
    int b  = rb >> 6;
    int m0 = rb << 6;
    int tx = t & 15, ty = t >> 4;

    // Q tile (persistent)
#pragma unroll
    for (int s = 0; s < 4; s++) {
        int li = t + s*256;           // 0..1023
        int r = li >> 4, dq = li & 15;
        float4 v = *(const float4*)(&g_Q[(size_t)(m0 + r)*DKq + dq*4]);
        *(float4*)(&Qs[r*QP + dq*4]) = v;
    }

    const float* gK = g_K + (size_t)b*Nq*DKq;
    float4* out4 = (float4*)out;
    size_t outBase4 = (size_t)m0 * (Nq/4);

    float vals[8]; int idx[8];
#pragma unroll
    for (int q = 0; q < 8; q++) { vals[q] = NEG_BIG; idx[q] = 0; }
    int rowb = t >> 2, part = t & 3;

    // prefetch K tile 0
#pragma unroll
    for (int s = 0; s < 4; s++) {
        int li = t + s*256;
        int r = li >> 4, seg = li & 15;
        unsigned dst = (unsigned)__cvta_generic_to_shared(&Ks0[r*QP + seg*4]);
        asm volatile("cp.async.cg.shared.global [%0], [%1], 16;"
                     :: "r"(dst), "l"(gK + (size_t)r*DKq + seg*4));
    }
    asm volatile("cp.async.commit_group;");

    const float4 z4 = make_float4(0.f, 0.f, 0.f, 0.f);

    for (int kt = 0; kt < 64; kt++) {
        float* Kbuf = Ks0 + (kt & 1)*KSF;
        if (kt < 63) {
            float* Knext = Ks0 + ((kt + 1) & 1)*KSF;
            const float* src = gK + (size_t)(kt + 1)*64*DKq;
#pragma unroll
            for (int s = 0; s < 4; s++) {
                int li = t + s*256;
                int r = li >> 4, seg = li & 15;
                unsigned dst = (unsigned)__cvta_generic_to_shared(&Knext[r*QP + seg*4]);
                asm volatile("cp.async.cg.shared.global [%0], [%1], 16;"
                             :: "r"(dst), "l"(src + (size_t)r*DKq + seg*4));
            }
            asm volatile("cp.async.commit_group;");
            asm volatile("cp.async.wait_group 1;");
        } else {
            asm volatile("cp.async.wait_group 0;");
        }
        __syncthreads();   // tile kt visible to all; previous Ss scan complete

        // interleaved zero-fill of this CTA's output rows (drains under compute)
#pragma unroll
        for (int s = 0; s < 4; s++)
            out4[outBase4 + (size_t)(kt*4 + s)*256 + t] = z4;

        // ---- GEMM: 64x64 S tile, f32x2 pairs over d ----
        unsigned long long acc[4][4];
#pragma unroll
        for (int i = 0; i < 4; i++)
#pragma unroll
            for (int j = 0; j < 4; j++) acc[i][j] = 0ull;
#pragma unroll
        for (int d = 0; d < DKq; d += 4) {
            ulonglong2 qv[4], kv[4];
#pragma unroll
            for (int i = 0; i < 4; i++)
                qv[i] = *(const ulonglong2*)(&Qs[(ty + 16*i)*QP + d]);
#pragma unroll
            for (int j = 0; j < 4; j++)
                kv[j] = *(const ulonglong2*)(&Kbuf[(tx + 16*j)*QP + d]);
#pragma unroll
            for (int i = 0; i < 4; i++)
#pragma unroll
                for (int j = 0; j < 4; j++) {
                    fma2(acc[i][j], qv[i].x, kv[j].x);
                    fma2(acc[i][j], qv[i].y, kv[j].y);
                }
        }
        // fold + stage scaled S tile
#pragma unroll
        for (int i = 0; i < 4; i++)
#pragma unroll
            for (int j = 0; j < 4; j++) {
                union { unsigned long long u; float2 f; } cv; cv.u = acc[i][j];
                Ss[(ty + 16*i)*QP + tx + 16*j] = (cv.f.x + cv.f.y) * 0.125f;
            }
        __syncthreads();

        // ---- top-8 scan: 4 threads per row, 16 cols each ----
        int kbase = kt*64 + part*16;
#pragma unroll
        for (int u = 0; u < 4; u++) {
            float4 sv = *(const float4*)(&Ss[rowb*QP + part*16 + u*4]);
            float ss[4] = {sv.x, sv.y, sv.z, sv.w};
#pragma unroll
            for (int w = 0; w < 4; w++) {
                float s = ss[w];
                if (s > vals[7]) {               // rare
                    float cv = s; int ci = kbase + u*4 + w;
#pragma unroll
                    for (int q = 0; q < 8; q++) {
                        if (cv > vals[q]) {
                            float tv = vals[q]; int ti = idx[q];
                            vals[q] = cv; idx[q] = ci; cv = tv; ci = ti;
                        }
                    }
                }
            }
        }
    }
    __syncthreads();

    // ---- merge 4 partial top-8 lists per row, softmax, sparse scatter ----
    float* MV = Ss;                 // 64 x 33 floats (conflict-free stride)
    int*   MI = (int*)Ks0;          // 64 x 33 ints
#pragma unroll
    for (int q = 0; q < 8; q++) {
        MV[rowb*33 + part*8 + q] = vals[q];
        MI[rowb*33 + part*8 + q] = idx[q];
    }
    __syncthreads();
    if (t < 64) {
        float bv[8]; int bi[8];
#pragma unroll
        for (int sel = 0; sel < 8; sel++) {
            float best = NEG_BIG; int bidx = 0, bslot = 0;
            for (int q = 0; q < 32; q++) {
                float v = MV[t*33 + q];
                if (v > best) { best = v; bidx = MI[t*33 + q]; bslot = q; }
            }
            bv[sel] = best; bi[sel] = bidx;
            MV[t*33 + bslot] = NEG_BIG;
        }
        float mx = bv[0];
        float e[8], Z = 0.f;
#pragma unroll
        for (int q = 0; q < 8; q++) { e[q] = expf(bv[q] - mx); Z += e[q]; }
        float inv = 1.0f / Z;
        size_t rowoff = (size_t)(m0 + t) * Nq;
#pragma unroll
        for (int q = 0; q < 8; q++) out[rowoff + bi[q]] = e[q] * inv;
    }
}

// =====================================================================
extern "C" void kernel_launch(void* const* d_in, const int* in_sizes, int n_in,
                              void* d_out, int out_size) {
    const float* x  = (const float*)d_in[0];
    const float* Wq = (const float*)d_in[1];
    const float* Wk = (const float*)d_in[2];
    float* out = (float*)d_out;

    cudaFuncSetAttribute(edge_kernel,
                         cudaFuncAttributeMaxDynamicSharedMemorySize, SM2_BYTES);

    proj_kernel<<<NROWS/64, 256>>>(x, Wq, Wk);
    edge_kernel<<<NROWS/64, 256, SM2_BYTES>>>(out);
}